// round 5
// baseline (speedup 1.0000x reference)
#include <cuda_runtime.h>
#include <math.h>

#define NL 4
#define BB 64
#define HH 1024
#define SS 256
#define GHH 512
#define H3 (3*HH)
#define KC 32
#define KCP 36
#define NST 3
#define STF (256*KCP)          // floats per pipeline stage (max M+TN = 256 rows)
#define NB 128                 // persistent grid: every phase = exactly 1 job/block
#define NT 512                 // 16 warps
#define SMEM_FLOATS (NST*STF + 2048)
#define SMEM_BYTES (SMEM_FLOATS*4)

// ---------------- device scratch (allocation-free: __device__ globals) ----------------
static __device__ float g_h [NL*BB*HH];
static __device__ float g_hg[NL*BB*HH];
static __device__ float g_sh[NL*BB*HH];
static __device__ float g_gi[NL*BB*H3];
static __device__ float g_gh[NL*BB*H3];
static __device__ float g_a1[NL*BB*2*HH];
static __device__ float g_a2[NL*BB*2*HH];
static __device__ float g_a3[NL*BB*2*HH];
static __device__ unsigned g_arrive;
static __device__ unsigned g_gen;
// TF32-pre-rounded weight copies (rounded once, streamed every step)
static __device__ float c_wih[NL*H3*HH];
static __device__ float c_whh[NL*H3*HH];
static __device__ float c_aw0[NL*HH*HH];
static __device__ float c_aw1[NL*GHH*GHH];
static __device__ float c_aw2[NL*GHH*GHH];
static __device__ float c_aw3[NL*HH*2*HH];

// ---------------- software grid barrier (all NB blocks resident) ----------------------
__device__ __forceinline__ void grid_sync()
{
  __syncthreads();
  if (threadIdx.x == 0) {
    unsigned gen = *(volatile unsigned*)&g_gen;
    __threadfence();
    unsigned a = atomicAdd(&g_arrive, 1u);
    if (a == gridDim.x - 1) {
      g_arrive = 0;
      __threadfence();
      *(volatile unsigned*)&g_gen = gen + 1u;
    } else {
      while (*(volatile unsigned*)&g_gen == gen) { __nanosleep(32); }
    }
    __threadfence();
  }
  __syncthreads();
}

// ---------------- small helpers --------------------------------------------------------
__device__ __forceinline__ unsigned f2tf(float v) {
  unsigned r; asm("cvt.rna.tf32.f32 %0, %1;" : "=r"(r) : "f"(v)); return r;
}
__device__ __forceinline__ void mma8(float* c, unsigned a0, unsigned a1,
                                     unsigned a2, unsigned a3,
                                     unsigned b0, unsigned b1) {
  asm volatile(
    "mma.sync.aligned.m16n8k8.row.col.f32.tf32.tf32.f32 "
    "{%0,%1,%2,%3}, {%4,%5,%6,%7}, {%8,%9}, {%0,%1,%2,%3};"
    : "+f"(c[0]), "+f"(c[1]), "+f"(c[2]), "+f"(c[3])
    : "r"(a0), "r"(a1), "r"(a2), "r"(a3), "r"(b0), "r"(b1));
}
__device__ __forceinline__ void cp16(float* s, const float* g) {
  unsigned a = (unsigned)__cvta_generic_to_shared(s);
  asm volatile("cp.async.cg.shared.global [%0], [%1], 16;" :: "r"(a), "l"(g));
}
__device__ __forceinline__ void cp4(float* s, const float* g) {
  unsigned a = (unsigned)__cvta_generic_to_shared(s);
  asm volatile("cp.async.ca.shared.global [%0], [%1], 4;" :: "r"(a), "l"(g));
}

// ---------------- M x TN TF32 GEMM tile, 3-stage cp.async pipeline ---------------------
// M = MW*16 rows (A rows >=64 come from A1), TN cols. W is pre-rounded tf32.
// 16 warps: wm = wid%MW (16 rows each), wn = wid/MW (TN*MW/16 cols each).
// GATHER folds the SortAttn shuffle into the A-load: src = (h%4)*512 + g*128 + h/4.
template<int MW, int TN, bool GATHER>
__device__ __forceinline__ void gemm_cp(
    const float* __restrict__ A0, const float* __restrict__ A1, long lda,
    const float* __restrict__ W, long ldw,
    int K, int g, float (*acc)[4], float* sm)
{
  constexpr int M = MW*16, NWN = 16/MW, CW = TN/NWN, NFR = CW/8;
  const int tid = threadIdx.x;
  const int lane = tid & 31, qr = lane >> 2, qc = lane & 3;
  const int wid = tid >> 5, wm = wid % MW, wn = wid / MW;
  const int mrow = wm*16, nbase = wn*CW;
#pragma unroll
  for (int j = 0; j < NFR; j++) { acc[j][0]=acc[j][1]=acc[j][2]=acc[j][3]=0.f; }
  const int NK = K / KC;

  auto issue = [&](int kt) {
    int k0 = kt * KC;
    float* As = sm + (kt % NST) * STF;
    float* Ws = As + M * KCP;
    if (!GATHER) {
      constexpr int ACH = M*KC/4;
#pragma unroll
      for (int p = 0; p < (ACH + NT - 1)/NT; p++) {
        int i = tid + p*NT;
        if (ACH % NT != 0 && i >= ACH) continue;
        int m = i >> 3, c = (i & 7) << 2;
        const float* src = (m < 64 ? A0 + (long)m*lda : A1 + (long)(m-64)*lda) + k0 + c;
        cp16(As + m*KCP + c, src);
      }
    } else {
#pragma unroll
      for (int p = 0; p < M*KC/NT; p++) {
        int i = tid + p*NT;
        int m = i >> 5, kc = i & 31, h = k0 + kc;
        int src = ((h & 3) << 9) + (g << 7) + (h >> 2);
        cp4(As + m*KCP + kc, A0 + (long)m*lda + src);
      }
    }
    constexpr int WCH = TN*KC/4;
#pragma unroll
    for (int p = 0; p < (WCH + NT - 1)/NT; p++) {
      int i = tid + p*NT;
      if (WCH % NT != 0 && i >= WCH) continue;
      int n = i >> 3, c = (i & 7) << 2;
      cp16(Ws + n*KCP + c, W + (long)n*ldw + k0 + c);
    }
  };

  // prologue: stages 0..NST-2
#pragma unroll
  for (int kt = 0; kt < NST-1; kt++) {
    if (kt < NK) issue(kt);
    asm volatile("cp.async.commit_group;");
  }
  for (int kt = 0; kt < NK; kt++) {
    asm volatile("cp.async.wait_group 1;");
    __syncthreads();
    if (kt + NST-1 < NK) issue(kt + NST-1);
    asm volatile("cp.async.commit_group;");
    const float* As = sm + (kt % NST) * STF;
    const float* Ws = As + M * KCP;
#pragma unroll
    for (int kk = 0; kk < KC; kk += 8) {
      unsigned a0 = f2tf(As[(mrow+qr  )*KCP + kk+qc  ]);
      unsigned a1 = f2tf(As[(mrow+qr+8)*KCP + kk+qc  ]);
      unsigned a2 = f2tf(As[(mrow+qr  )*KCP + kk+qc+4]);
      unsigned a3 = f2tf(As[(mrow+qr+8)*KCP + kk+qc+4]);
#pragma unroll
      for (int j = 0; j < NFR; j++) {
        unsigned b0 = __float_as_uint(Ws[(nbase+j*8+qr)*KCP + kk+qc  ]);
        unsigned b1 = __float_as_uint(Ws[(nbase+j*8+qr)*KCP + kk+qc+4]);
        mma8(acc[j], a0, a1, a2, a3, b0, b1);
      }
    }
  }
  __syncthreads();   // protect stage smem before next job's prologue
}

// ---------------- init / prep kernels --------------------------------------------------
__global__ void k_init(const float* __restrict__ h0)
{
  int idx = blockIdx.x*256 + threadIdx.x;
  if (idx == 0) { g_arrive = 0u; g_gen = 0u; }
  int l = idx / (BB*HH);
  int j = idx & (HH-1);
  g_h[idx] = h0[l*HH + j];
}
__global__ void k_round(const float* __restrict__ src, float* __restrict__ dst, int n)
{
  for (int i = blockIdx.x*blockDim.x + threadIdx.x; i < n; i += gridDim.x*blockDim.x)
    dst[i] = __uint_as_float(f2tf(src[i]));
}

// ---------------- persistent main kernel ----------------------------------------------
__global__ void __launch_bounds__(NT, 1) k_main(
    const float* __restrict__ x,
    const float* __restrict__ bih, const float* __restrict__ bhh,
    float* __restrict__ out, int write_ht)
{
  extern __shared__ float sm[];
  float* ssort = sm + NST*STF;
  const int tid = threadIdx.x;
  const int lane = tid & 31, qr = lane >> 2, qc = lane & 3;
  const int wid = tid >> 5;
  const int blk = blockIdx.x;

  for (int step = 0; step < SS + NL - 1; step++) {

    // ---- P1: gi = inp @ Wih^T + bih ; gh = h @ Whh^T + bhh  (128 jobs, TN=192) ----
    {
      int l = blk >> 5, mat = (blk >> 4) & 1, nt = blk & 15;
      int t = step - l;
      if (t >= 0 && t < SS) {
        int n0 = nt * 192;
        const float* A; long lda; const float* W; const float* bias; float* C;
        if (mat == 0) {
          if (l == 0) { A = x + (long)t*HH; lda = (long)SS*HH; }
          else        { A = g_h + (long)(l-1)*BB*HH; lda = HH; }
          W = c_wih + (long)l*H3*HH + (long)n0*HH;
          bias = bih + l*H3 + n0;  C = g_gi + (long)l*BB*H3;
        } else {
          A = g_h + (long)l*BB*HH; lda = HH;
          W = c_whh + (long)l*H3*HH + (long)n0*HH;
          bias = bhh + l*H3 + n0;  C = g_gh + (long)l*BB*H3;
        }
        float acc[6][4];
        gemm_cp<4,192,false>(A, A, lda, W, HH, HH, 0, acc, sm);
        int wm = wid & 3, wn = wid >> 2, mrow = wm*16, nb = wn*48;
#pragma unroll
        for (int j = 0; j < 6; j++) {
          int nl = nb + j*8 + 2*qc;
          float2 v0 = make_float2(acc[j][0] + bias[nl], acc[j][1] + bias[nl+1]);
          float2 v1 = make_float2(acc[j][2] + bias[nl], acc[j][3] + bias[nl+1]);
          *reinterpret_cast<float2*>(&C[(long)(mrow+qr  )*H3 + n0 + nl]) = v0;
          *reinterpret_cast<float2*>(&C[(long)(mrow+qr+8)*H3 + n0 + nl]) = v1;
        }
      }
    }
    grid_sync();

    // ---- P2: gates + sort. 2 rows per block, 256 threads each, named barriers ----
    {
      int h = tid >> 8, htid = tid & 255;
      int jb = blk*2 + h;
      int l = jb >> 6, b = jb & 63;
      int t = step - l;
      if (t >= 0 && t < SS) {
        float* s = ssort + h*1024;
        long gb = (long)(l*BB + b)*H3;
        long hb = (long)(l*BB + b)*HH;
#pragma unroll
        for (int p = 0; p < 4; p++) {
          int j = htid + p*256;
          float ir = g_gi[gb + j], iz = g_gi[gb + HH + j], in = g_gi[gb + 2*HH + j];
          float hr = g_gh[gb + j], hz = g_gh[gb + HH + j], hn = g_gh[gb + 2*HH + j];
          float rr = 1.f/(1.f + expf(-(ir + hr)));
          float zz = 1.f/(1.f + expf(-(iz + hz)));
          float nn = tanhf(in + rr*hn);
          float hv = (1.f - zz)*nn + zz*g_h[hb + j];
          g_hg[hb + j] = hv;
          s[j] = hv;
        }
        asm volatile("bar.sync %0, 256;" :: "r"(1+h) : "memory");
        // bitonic: strides <=32 are warp-local (64-elem windows) -> syncwarp only
        for (int size = 2; size <= 1024; size <<= 1) {
          for (int stride = size >> 1; stride; stride >>= 1) {
            if (stride >= 64) asm volatile("bar.sync %0, 256;" :: "r"(1+h) : "memory");
#pragma unroll
            for (int p = 0; p < 2; p++) {
              int q = htid + p*256;
              int pos = 2*q - (q & (stride - 1));
              float a = s[pos], c = s[pos + stride];
              bool desc = (pos & size) != 0;
              if ((a > c) != desc) { s[pos] = c; s[pos + stride] = a; }
            }
            if (stride >= 64) asm volatile("bar.sync %0, 256;" :: "r"(1+h) : "memory");
            else __syncwarp();
          }
        }
#pragma unroll
        for (int p = 0; p < 4; p++) { int j = htid + p*256; g_sh[hb + j] = s[j]; }
      }
    }
    grid_sync();

    // ---- P3: a1 = [hg; sh] @ w0^T  (M=128 fused, 128 jobs, TN=32) ----
    {
      int l = blk >> 5, nt = blk & 31;
      int t = step - l;
      if (t >= 0 && t < SS) {
        int n0 = nt * 32;
        const float* W = c_aw0 + (long)l*HH*HH + (long)n0*HH;
        float* C = g_a1 + (long)l*BB*2*HH;
        float acc[2][4];
        gemm_cp<8,32,false>(g_hg + (long)l*BB*HH, g_sh + (long)l*BB*HH, HH,
                            W, HH, HH, 0, acc, sm);
        int wm = wid & 7, wn = wid >> 3, mrow = wm*16, nb = wn*16;
        int y = mrow >> 6;                 // rows >=64 are the sorted half
        int b0r = mrow & 63;
#pragma unroll
        for (int j = 0; j < 2; j++) {
          int nl = nb + j*8 + 2*qc;
          *reinterpret_cast<float2*>(&C[(long)(b0r+qr  )*2*HH + y*HH + n0 + nl]) =
              make_float2(acc[j][0], acc[j][1]);
          *reinterpret_cast<float2*>(&C[(long)(b0r+qr+8)*2*HH + y*HH + n0 + nl]) =
              make_float2(acc[j][2], acc[j][3]);
        }
      }
    }
    grid_sync();

    // ---- P4: w1 GEMM, folded shuffle gather (128 jobs, TN=64) ----
    {
      int l = blk >> 5, g4 = (blk >> 3) & 3, nt = blk & 7;
      int t = step - l;
      if (t >= 0 && t < SS) {
        int n0 = nt * 64;
        const float* A = g_a1 + (long)l*BB*2*HH;
        const float* W = c_aw1 + (long)l*GHH*GHH + (long)n0*GHH;
        float* C = g_a2 + (long)l*BB*2*HH;
        float acc[2][4];
        gemm_cp<4,64,true>(A, A, 2*HH, W, GHH, GHH, g4, acc, sm);
        int wm = wid & 3, wn = wid >> 2, mrow = wm*16, nb = wn*16;
#pragma unroll
        for (int j = 0; j < 2; j++) {
          int nl = nb + j*8 + 2*qc;
          *reinterpret_cast<float2*>(&C[(long)(mrow+qr  )*2*HH + g4*GHH + n0 + nl]) =
              make_float2(acc[j][0], acc[j][1]);
          *reinterpret_cast<float2*>(&C[(long)(mrow+qr+8)*2*HH + g4*GHH + n0 + nl]) =
              make_float2(acc[j][2], acc[j][3]);
        }
      }
    }
    grid_sync();

    // ---- P5: w2 GEMM, folded shuffle gather + ReLU (128 jobs, TN=64) ----
    {
      int l = blk >> 5, g4 = (blk >> 3) & 3, nt = blk & 7;
      int t = step - l;
      if (t >= 0 && t < SS) {
        int n0 = nt * 64;
        const float* A = g_a2 + (long)l*BB*2*HH;
        const float* W = c_aw2 + (long)l*GHH*GHH + (long)n0*GHH;
        float* C = g_a3 + (long)l*BB*2*HH;
        float acc[2][4];
        gemm_cp<4,64,true>(A, A, 2*HH, W, GHH, GHH, g4, acc, sm);
        int wm = wid & 3, wn = wid >> 2, mrow = wm*16, nb = wn*16;
#pragma unroll
        for (int j = 0; j < 2; j++) {
          int nl = nb + j*8 + 2*qc;
          float2 v0 = make_float2(fmaxf(acc[j][0],0.f), fmaxf(acc[j][1],0.f));
          float2 v1 = make_float2(fmaxf(acc[j][2],0.f), fmaxf(acc[j][3],0.f));
          *reinterpret_cast<float2*>(&C[(long)(mrow+qr  )*2*HH + g4*GHH + n0 + nl]) = v0;
          *reinterpret_cast<float2*>(&C[(long)(mrow+qr+8)*2*HH + g4*GHH + n0 + nl]) = v1;
        }
      }
    }
    grid_sync();

    // ---- P6: w3 GEMM (K=2048, 128 jobs, TN=32) + fused sigmoid gate ----
    {
      int l = blk >> 5, nt = blk & 31;
      int t = step - l;
      if (t >= 0 && t < SS) {
        int n0 = nt * 32;
        const float* A = g_a3 + (long)l*BB*2*HH;
        const float* W = c_aw3 + (long)l*HH*2*HH + (long)n0*2*HH;
        float acc[1][4];
        gemm_cp<4,32,false>(A, A, 2*HH, W, 2*HH, 2*HH, 0, acc, sm);
        int wm = wid & 3, wn = wid >> 2, mrow = wm*16;
        int nl = wn*8 + 2*qc;
        int n = n0 + nl;
#pragma unroll
        for (int half = 0; half < 2; half++) {
          int b = mrow + qr + half*8;
          long hb = (long)(l*BB + b)*HH + n;
#pragma unroll
          for (int jj = 0; jj < 2; jj++) {
            float a = acc[0][half*2 + jj];
            float res = g_hg[hb + jj] * (1.f/(1.f + expf(-a)));
            g_h[hb + jj] = res;
            if (l == NL-1) out[((long)b*SS + t)*HH + n + jj] = res;
            if (write_ht && t == SS-1) out[(long)BB*SS*HH + hb + jj] = res;
          }
        }
      }
    }
    grid_sync();
  }
}

// ---------------- host ------------------------------------------------------------------
extern "C" void kernel_launch(void* const* d_in, const int* in_sizes, int n_in,
                              void* d_out, int out_size)
{
  const float* x   = (const float*)d_in[0];
  const float* h0  = (const float*)d_in[1];
  const float* Wih = (const float*)d_in[2];
  const float* Whh = (const float*)d_in[3];
  const float* bih = (const float*)d_in[4];
  const float* bhh = (const float*)d_in[5];
  const float* aw0 = (const float*)d_in[6];
  const float* aw1 = (const float*)d_in[7];
  const float* aw2 = (const float*)d_in[8];
  const float* aw3 = (const float*)d_in[9];
  float* out = (float*)d_out;

  int write_ht = (out_size >= BB*SS*HH + NL*BB*HH) ? 1 : 0;

  cudaFuncSetAttribute(k_main, cudaFuncAttributeMaxDynamicSharedMemorySize, SMEM_BYTES);

  // one-time per launch: round weights to tf32 into device scratch
  float* dsts[6]; const float* srcs[6]; int ns[6];
  cudaGetSymbolAddress((void**)&dsts[0], c_wih); srcs[0] = Wih; ns[0] = NL*H3*HH;
  cudaGetSymbolAddress((void**)&dsts[1], c_whh); srcs[1] = Whh; ns[1] = NL*H3*HH;
  cudaGetSymbolAddress((void**)&dsts[2], c_aw0); srcs[2] = aw0; ns[2] = NL*HH*HH;
  cudaGetSymbolAddress((void**)&dsts[3], c_aw1); srcs[3] = aw1; ns[3] = NL*GHH*GHH;
  cudaGetSymbolAddress((void**)&dsts[4], c_aw2); srcs[4] = aw2; ns[4] = NL*GHH*GHH;
  cudaGetSymbolAddress((void**)&dsts[5], c_aw3); srcs[5] = aw3; ns[5] = NL*HH*2*HH;
  for (int i = 0; i < 6; i++)
    k_round<<<512, 256>>>(srcs[i], dsts[i], ns[i]);

  k_init<<<NL*BB*HH/256, 256>>>(h0);
  k_main<<<NB, NT, SMEM_BYTES>>>(x, bih, bhh, out, write_ht);
}

// round 6
// speedup vs baseline: 1.3543x; 1.3543x over previous
#include <cuda_runtime.h>
#include <math.h>

#define NL 4
#define BB 64
#define HH 1024
#define SS 256
#define GHH 512
#define H3 (3*HH)
#define KC 64
#define KCP 68
#define NB 148                 // persistent grid: <= SM count, all co-resident
#define NT 512                 // 16 warps
#define SMEM_FLOATS (160*KCP + 2048)
#define SMEM_BYTES (SMEM_FLOATS*4)

// ---------------- device scratch (allocation-free: __device__ globals) ----------------
static __device__ float g_h [NL*BB*HH];
static __device__ float g_hg[NL*BB*HH];
static __device__ float g_sh[NL*BB*HH];
static __device__ float g_gi[NL*BB*H3];
static __device__ float g_gh[NL*BB*H3];
static __device__ float g_gi0[(long)SS*BB*H3];  // precomputed x@Wih0^T + bih0 per t
static __device__ float g_a1[NL*BB*2*HH];
static __device__ float g_a2[NL*BB*2*HH];
static __device__ float g_a3[NL*BB*2*HH];
static __device__ unsigned g_arrive;
static __device__ unsigned g_gen;
// TF32-pre-rounded weights (rounded once, streamed every step)
static __device__ float c_wih[NL*H3*HH];
static __device__ float c_whh[NL*H3*HH];
static __device__ float c_aw0[NL*HH*HH];
static __device__ float c_aw1[NL*GHH*GHH];
static __device__ float c_aw2[NL*GHH*GHH];
static __device__ float c_aw3[NL*HH*2*HH];

// ---------------- software grid barrier -------------------------------------------------
__device__ __forceinline__ void grid_sync()
{
  __syncthreads();
  if (threadIdx.x == 0) {
    unsigned gen = *(volatile unsigned*)&g_gen;
    __threadfence();
    unsigned a = atomicAdd(&g_arrive, 1u);
    if (a == gridDim.x - 1) {
      g_arrive = 0;
      __threadfence();
      *(volatile unsigned*)&g_gen = gen + 1u;
    } else {
      while (*(volatile unsigned*)&g_gen == gen) { __nanosleep(32); }
    }
    __threadfence();
  }
  __syncthreads();
}

// ---------------- helpers ---------------------------------------------------------------
__device__ __forceinline__ unsigned f2tf(float v) {
  unsigned r; asm("cvt.rna.tf32.f32 %0, %1;" : "=r"(r) : "f"(v)); return r;
}
__device__ __forceinline__ void mma8(float* c, unsigned a0, unsigned a1,
                                     unsigned a2, unsigned a3,
                                     unsigned b0, unsigned b1) {
  asm volatile(
    "mma.sync.aligned.m16n8k8.row.col.f32.tf32.tf32.f32 "
    "{%0,%1,%2,%3}, {%4,%5,%6,%7}, {%8,%9}, {%0,%1,%2,%3};"
    : "+f"(c[0]), "+f"(c[1]), "+f"(c[2]), "+f"(c[3])
    : "r"(a0), "r"(a1), "r"(a2), "r"(a3), "r"(b0), "r"(b1));
}

// ---------------- register-staged M x TN TF32 GEMM: C = A(M,K) @ W(TN,K)^T --------------
// 16 warps: wm = wid%MW (16 rows), wn = wid/MW (CW cols). W is pre-rounded tf32 bits.
// A rows >= 64 come from A1 (used by the fused P3). GATHER folds the SortAttn shuffle:
// src = (h%4)*512 + g*128 + h/4.
template<int MW, int TN, bool GATHER>
__device__ __forceinline__ void gemm_rs(
    const float* __restrict__ A0, const float* __restrict__ A1, long lda,
    const float* __restrict__ W, long ldw, int K, int g,
    float (*acc)[4], unsigned* smbase)
{
  constexpr int M = MW*16;
  constexpr int CW = TN*MW/16;
  constexpr int NFR = CW/8;
  constexpr int NA4 = M*16/NT;          // A float4 loads/thread (KC=64)
  constexpr int NW4 = TN*16/NT;         // W float4 loads/thread
  unsigned* As = smbase;
  unsigned* Ws = smbase + M*KCP;
  const int tid = threadIdx.x;
  const int lane = tid & 31, qr = lane >> 2, qc = lane & 3;
  const int wid = tid >> 5, wm = wid % MW, wn = wid / MW;
  const int mrow = wm*16, nbase = wn*CW;
#pragma unroll
  for (int j = 0; j < NFR; j++) { acc[j][0]=acc[j][1]=acc[j][2]=acc[j][3]=0.f; }

  float4 a4[NA4 ? NA4 : 1];
  float  ag[8];
  float4 w4[NW4];
  const int NK = K / KC;

  // stage tile 0
  if (!GATHER) {
#pragma unroll
    for (int p = 0; p < NA4; p++) {
      int i = tid + p*NT; int m = i >> 4, c = (i & 15) << 2;
      const float* src = (M > 64 && m >= 64) ? A1 + (long)(m-64)*lda : A0 + (long)m*lda;
      a4[p] = *reinterpret_cast<const float4*>(src + c);
    }
  } else {
#pragma unroll
    for (int p = 0; p < 8; p++) {
      int i = tid + p*NT; int m = i >> 6; int h = i & 63;
      int s = ((h & 3) << 9) + (g << 7) + (h >> 2);
      ag[p] = A0[(long)m*lda + s];
    }
  }
#pragma unroll
  for (int p = 0; p < NW4; p++) {
    int i = tid + p*NT; int n = i >> 4, c = (i & 15) << 2;
    w4[p] = *reinterpret_cast<const float4*>(W + (long)n*ldw + c);
  }

  for (int kt = 0; kt < NK; kt++) {
    __syncthreads();                    // previous tile's compute done
    if (!GATHER) {
#pragma unroll
      for (int p = 0; p < NA4; p++) {
        int i = tid + p*NT; int m = i >> 4, c = (i & 15) << 2;
        uint4 v = make_uint4(f2tf(a4[p].x), f2tf(a4[p].y), f2tf(a4[p].z), f2tf(a4[p].w));
        *reinterpret_cast<uint4*>(&As[m*KCP + c]) = v;
      }
    } else {
#pragma unroll
      for (int p = 0; p < 8; p++) {
        int i = tid + p*NT; int m = i >> 6, kc = i & 63;
        As[m*KCP + kc] = f2tf(ag[p]);
      }
    }
#pragma unroll
    for (int p = 0; p < NW4; p++) {     // W already tf32 bits: raw copy
      int i = tid + p*NT; int n = i >> 4, c = (i & 15) << 2;
      *reinterpret_cast<uint4*>(&Ws[n*KCP + c]) = *reinterpret_cast<uint4*>(&w4[p]);
    }
    __syncthreads();
    int k1 = (kt + 1) * KC;
    if (kt + 1 < NK) {                  // stage next tile (overlaps with compute)
      if (!GATHER) {
#pragma unroll
        for (int p = 0; p < NA4; p++) {
          int i = tid + p*NT; int m = i >> 4, c = (i & 15) << 2;
          const float* src = (M > 64 && m >= 64) ? A1 + (long)(m-64)*lda : A0 + (long)m*lda;
          a4[p] = *reinterpret_cast<const float4*>(src + k1 + c);
        }
      } else {
#pragma unroll
        for (int p = 0; p < 8; p++) {
          int i = tid + p*NT; int m = i >> 6; int h = k1 + (i & 63);
          int s = ((h & 3) << 9) + (g << 7) + (h >> 2);
          ag[p] = A0[(long)m*lda + s];
        }
      }
#pragma unroll
      for (int p = 0; p < NW4; p++) {
        int i = tid + p*NT; int n = i >> 4, c = (i & 15) << 2;
        w4[p] = *reinterpret_cast<const float4*>(W + (long)n*ldw + k1 + c);
      }
    }
#pragma unroll
    for (int kk = 0; kk < KC; kk += 8) {
      unsigned a0 = As[(mrow+qr  )*KCP + kk+qc  ];
      unsigned a1 = As[(mrow+qr+8)*KCP + kk+qc  ];
      unsigned a2 = As[(mrow+qr  )*KCP + kk+qc+4];
      unsigned a3 = As[(mrow+qr+8)*KCP + kk+qc+4];
#pragma unroll
      for (int j = 0; j < NFR; j++) {
        unsigned b0 = Ws[(nbase+j*8+qr)*KCP + kk+qc  ];
        unsigned b1 = Ws[(nbase+j*8+qr)*KCP + kk+qc+4];
        mma8(acc[j], a0, a1, a2, a3, b0, b1);
      }
    }
  }
}

// ---------------- init / prep kernels ---------------------------------------------------
__global__ void k_init(const float* __restrict__ h0)
{
  int idx = blockIdx.x*256 + threadIdx.x;
  if (idx == 0) { g_arrive = 0u; g_gen = 0u; }
  int l = idx / (BB*HH);
  int j = idx & (HH-1);
  g_h[idx] = h0[l*HH + j];
}
__global__ void k_round(const float* __restrict__ src, float* __restrict__ dst, int n)
{
  for (int i = blockIdx.x*blockDim.x + threadIdx.x; i < n; i += gridDim.x*blockDim.x)
    dst[i] = __uint_as_float(f2tf(src[i]));
}

// one-time: g_gi0[t] = x[:,t,:] @ Wih0^T + bih0 for all t (layer 0 input GEMM)
__global__ void __launch_bounds__(NT, 1) k_pre(const float* __restrict__ x,
                                               const float* __restrict__ bih)
{
  extern __shared__ unsigned smu[];
  int nt = blockIdx.x, t = blockIdx.y;
  int n0 = nt * 96;
  const float* A = x + (long)t*HH;                  // row b -> x[b*S*H + t*H]
  const float* W = c_wih + (long)n0*HH;             // layer 0
  float* C = g_gi0 + (long)t*BB*H3;
  float acc[3][4];
  gemm_rs<4,96,false>(A, A, (long)SS*HH, W, HH, HH, 0, acc, smu);
  const int tid = threadIdx.x, lane = tid & 31, qr = lane >> 2, qc = lane & 3;
  const int wid = tid >> 5, wm = wid & 3, wn = wid >> 2, mrow = wm*16, nb = wn*24;
#pragma unroll
  for (int j = 0; j < 3; j++) {
    int nl = nb + j*8 + 2*qc;
    float b0v = bih[n0+nl], b1v = bih[n0+nl+1];
    *reinterpret_cast<float2*>(&C[(long)(mrow+qr  )*H3 + n0 + nl]) =
        make_float2(acc[j][0]+b0v, acc[j][1]+b1v);
    *reinterpret_cast<float2*>(&C[(long)(mrow+qr+8)*H3 + n0 + nl]) =
        make_float2(acc[j][2]+b0v, acc[j][3]+b1v);
  }
}

// ---------------- persistent main kernel ------------------------------------------------
__global__ void __launch_bounds__(NT, 1) k_main(
    const float* __restrict__ bih, const float* __restrict__ bhh,
    float* __restrict__ out, int write_ht)
{
  extern __shared__ unsigned smu[];
  float* ssort = reinterpret_cast<float*>(smu) + 160*KCP;
  const int tid = threadIdx.x;
  const int lane = tid & 31, qr = lane >> 2, qc = lane & 3;
  const int wid = tid >> 5;
  const int blk = blockIdx.x;

  for (int step = 0; step < SS + NL - 1; step++) {

    // ---- P1: 7 weight matrices (Wih l=1..3, Whh l=0..3) x 32 N-tiles of 96 = 224 jobs ----
    for (int job = blk; job < 224; job += NB) {
      int mi = job >> 5, nt = job & 31;
      int l, isWih;
      if (mi < 3) { isWih = 1; l = mi + 1; } else { isWih = 0; l = mi - 3; }
      int t = step - l; if (t < 0 || t >= SS) continue;
      int n0 = nt * 96;
      const float* A; const float* W; const float* bias; float* C;
      if (isWih) {
        A = g_h + (long)(l-1)*BB*HH;
        W = c_wih + (long)l*H3*HH + (long)n0*HH;
        bias = bih + l*H3 + n0;  C = g_gi + (long)l*BB*H3;
      } else {
        A = g_h + (long)l*BB*HH;
        W = c_whh + (long)l*H3*HH + (long)n0*HH;
        bias = bhh + l*H3 + n0;  C = g_gh + (long)l*BB*H3;
      }
      float acc[3][4];
      gemm_rs<4,96,false>(A, A, HH, W, HH, HH, 0, acc, smu);
      int wm = wid & 3, wn = wid >> 2, mrow = wm*16, nb = wn*24;
#pragma unroll
      for (int j = 0; j < 3; j++) {
        int nl = nb + j*8 + 2*qc;
        float b0v = bias[nl], b1v = bias[nl+1];
        *reinterpret_cast<float2*>(&C[(long)(mrow+qr  )*H3 + n0 + nl]) =
            make_float2(acc[j][0]+b0v, acc[j][1]+b1v);
        *reinterpret_cast<float2*>(&C[(long)(mrow+qr+8)*H3 + n0 + nl]) =
            make_float2(acc[j][2]+b0v, acc[j][3]+b1v);
      }
    }
    grid_sync();

    // ---- P2: gates + sort. 2 rows/block, 256 threads each, named barriers ----
    if (blk < 128) {
      int h = tid >> 8, htid = tid & 255;
      int jb = blk*2 + h;
      int l = jb >> 6, b = jb & 63;
      int t = step - l;
      if (t >= 0 && t < SS) {
        float* s = ssort + h*1024;
        const float* gi = (l == 0) ? g_gi0 + ((long)t*BB + b)*H3
                                   : g_gi + (long)(l*BB + b)*H3;
        long gb = (long)(l*BB + b)*H3;
        long hb = (long)(l*BB + b)*HH;
#pragma unroll
        for (int p = 0; p < 4; p++) {
          int j = htid + p*256;
          float ir = gi[j], iz = gi[HH + j], in = gi[2*HH + j];
          float hr = g_gh[gb + j], hz = g_gh[gb + HH + j], hn = g_gh[gb + 2*HH + j];
          float rr = 1.f/(1.f + expf(-(ir + hr)));
          float zz = 1.f/(1.f + expf(-(iz + hz)));
          float nn = tanhf(in + rr*hn);
          float hv = (1.f - zz)*nn + zz*g_h[hb + j];
          g_hg[hb + j] = hv;
          s[j] = hv;
        }
        asm volatile("bar.sync %0, 256;" :: "r"(1+h) : "memory");
        for (int size = 2; size <= 1024; size <<= 1) {
          for (int stride = size >> 1; stride; stride >>= 1) {
            if (stride >= 64) asm volatile("bar.sync %0, 256;" :: "r"(1+h) : "memory");
#pragma unroll
            for (int p = 0; p < 2; p++) {
              int q = htid + p*256;
              int pos = 2*q - (q & (stride - 1));
              float a = s[pos], c = s[pos + stride];
              bool desc = (pos & size) != 0;
              if ((a > c) != desc) { s[pos] = c; s[pos + stride] = a; }
            }
            if (stride >= 64) asm volatile("bar.sync %0, 256;" :: "r"(1+h) : "memory");
            else __syncwarp();
          }
        }
#pragma unroll
        for (int p = 0; p < 4; p++) { int j = htid + p*256; g_sh[hb + j] = s[j]; }
      }
    }
    grid_sync();

    // ---- P3: a1 = [hg; sh] @ w0^T  (M=128 fused, TN=32, 128 jobs) ----
    if (blk < 128) {
      int l = blk >> 5, nt = blk & 31;
      int t = step - l;
      if (t >= 0 && t < SS) {
        int n0 = nt * 32;
        const float* W = c_aw0 + (long)l*HH*HH + (long)n0*HH;
        float* C = g_a1 + (long)l*BB*2*HH;
        float acc[2][4];
        gemm_rs<8,32,false>(g_hg + (long)l*BB*HH, g_sh + (long)l*BB*HH, HH,
                            W, HH, HH, 0, acc, smu);
        int wm = wid & 7, wn = wid >> 3, mrow = wm*16, nb = wn*16;
        int y = mrow >> 6, b0r = mrow & 63;
#pragma unroll
        for (int j = 0; j < 2; j++) {
          int nl = nb + j*8 + 2*qc;
          *reinterpret_cast<float2*>(&C[(long)(b0r+qr  )*2*HH + y*HH + n0 + nl]) =
              make_float2(acc[j][0], acc[j][1]);
          *reinterpret_cast<float2*>(&C[(long)(b0r+qr+8)*2*HH + y*HH + n0 + nl]) =
              make_float2(acc[j][2], acc[j][3]);
        }
      }
    }
    grid_sync();

    // ---- P4: w1 GEMM, folded shuffle gather (TN=64, 128 jobs) ----
    if (blk < 128) {
      int l = blk >> 5, g4 = (blk >> 3) & 3, nt = blk & 7;
      int t = step - l;
      if (t >= 0 && t < SS) {
        int n0 = nt * 64;
        const float* A = g_a1 + (long)l*BB*2*HH;
        const float* W = c_aw1 + (long)l*GHH*GHH + (long)n0*GHH;
        float* C = g_a2 + (long)l*BB*2*HH;
        float acc[2][4];
        gemm_rs<4,64,true>(A, A, 2*HH, W, GHH, GHH, g4, acc, smu);
        int wm = wid & 3, wn = wid >> 2, mrow = wm*16, nb = wn*16;
#pragma unroll
        for (int j = 0; j < 2; j++) {
          int nl = nb + j*8 + 2*qc;
          *reinterpret_cast<float2*>(&C[(long)(mrow+qr  )*2*HH + g4*GHH + n0 + nl]) =
              make_float2(acc[j][0], acc[j][1]);
          *reinterpret_cast<float2*>(&C[(long)(mrow+qr+8)*2*HH + g4*GHH + n0 + nl]) =
              make_float2(acc[j][2], acc[j][3]);
        }
      }
    }
    grid_sync();

    // ---- P5: w2 GEMM, folded shuffle gather + ReLU (TN=64, 128 jobs) ----
    if (blk < 128) {
      int l = blk >> 5, g4 = (blk >> 3) & 3, nt = blk & 7;
      int t = step - l;
      if (t >= 0 && t < SS) {
        int n0 = nt * 64;
        const float* A = g_a2 + (long)l*BB*2*HH;
        const float* W = c_aw2 + (long)l*GHH*GHH + (long)n0*GHH;
        float* C = g_a3 + (long)l*BB*2*HH;
        float acc[2][4];
        gemm_rs<4,64,true>(A, A, 2*HH, W, GHH, GHH, g4, acc, smu);
        int wm = wid & 3, wn = wid >> 2, mrow = wm*16, nb = wn*16;
#pragma unroll
        for (int j = 0; j < 2; j++) {
          int nl = nb + j*8 + 2*qc;
          float2 v0 = make_float2(fmaxf(acc[j][0],0.f), fmaxf(acc[j][1],0.f));
          float2 v1 = make_float2(fmaxf(acc[j][2],0.f), fmaxf(acc[j][3],0.f));
          *reinterpret_cast<float2*>(&C[(long)(mrow+qr  )*2*HH + g4*GHH + n0 + nl]) = v0;
          *reinterpret_cast<float2*>(&C[(long)(mrow+qr+8)*2*HH + g4*GHH + n0 + nl]) = v1;
        }
      }
    }
    grid_sync();

    // ---- P6: w3 GEMM (K=2048, TN=32, 128 jobs) + fused sigmoid gate ----
    if (blk < 128) {
      int l = blk >> 5, nt = blk & 31;
      int t = step - l;
      if (t >= 0 && t < SS) {
        int n0 = nt * 32;
        const float* A = g_a3 + (long)l*BB*2*HH;
        const float* W = c_aw3 + (long)l*HH*2*HH + (long)n0*2*HH;
        float acc[1][4];
        gemm_rs<4,32,false>(A, A, 2*HH, W, 2*HH, 2*HH, 0, acc, smu);
        int wm = wid & 3, wn = wid >> 2, mrow = wm*16;
        int nl = wn*8 + 2*qc;
        int n = n0 + nl;
#pragma unroll
        for (int half = 0; half < 2; half++) {
          int b = mrow + qr + half*8;
          long hb = (long)(l*BB + b)*HH + n;
#pragma unroll
          for (int jj = 0; jj < 2; jj++) {
            float a = acc[0][half*2 + jj];
            float res = g_hg[hb + jj] * (1.f/(1.f + expf(-a)));
            g_h[hb + jj] = res;
            if (l == NL-1) out[((long)b*SS + t)*HH + n + jj] = res;
            if (write_ht && t == SS-1) out[(long)BB*SS*HH + hb + jj] = res;
          }
        }
      }
    }
    grid_sync();
  }
}

// ---------------- host ------------------------------------------------------------------
extern "C" void kernel_launch(void* const* d_in, const int* in_sizes, int n_in,
                              void* d_out, int out_size)
{
  const float* x   = (const float*)d_in[0];
  const float* h0  = (const float*)d_in[1];
  const float* Wih = (const float*)d_in[2];
  const float* Whh = (const float*)d_in[3];
  const float* bih = (const float*)d_in[4];
  const float* bhh = (const float*)d_in[5];
  const float* aw0 = (const float*)d_in[6];
  const float* aw1 = (const float*)d_in[7];
  const float* aw2 = (const float*)d_in[8];
  const float* aw3 = (const float*)d_in[9];
  float* out = (float*)d_out;

  int write_ht = (out_size >= BB*SS*HH + NL*BB*HH) ? 1 : 0;

  cudaFuncSetAttribute(k_pre,  cudaFuncAttributeMaxDynamicSharedMemorySize, SMEM_BYTES);
  cudaFuncSetAttribute(k_main, cudaFuncAttributeMaxDynamicSharedMemorySize, SMEM_BYTES);

  // round weights to tf32 once
  float* dsts[6]; const float* srcs[6]; int ns[6];
  cudaGetSymbolAddress((void**)&dsts[0], c_wih); srcs[0] = Wih; ns[0] = NL*H3*HH;
  cudaGetSymbolAddress((void**)&dsts[1], c_whh); srcs[1] = Whh; ns[1] = NL*H3*HH;
  cudaGetSymbolAddress((void**)&dsts[2], c_aw0); srcs[2] = aw0; ns[2] = NL*HH*HH;
  cudaGetSymbolAddress((void**)&dsts[3], c_aw1); srcs[3] = aw1; ns[3] = NL*GHH*GHH;
  cudaGetSymbolAddress((void**)&dsts[4], c_aw2); srcs[4] = aw2; ns[4] = NL*GHH*GHH;
  cudaGetSymbolAddress((void**)&dsts[5], c_aw3); srcs[5] = aw3; ns[5] = NL*HH*2*HH;
  for (int i = 0; i < 6; i++)
    k_round<<<512, 256>>>(srcs[i], dsts[i], ns[i]);

  k_init<<<NL*BB*HH/256, 256>>>(h0);
  k_pre<<<dim3(32, 256), NT, SMEM_BYTES>>>(x, bih);     // layer-0 input GEMM, all t
  k_main<<<NB, NT, SMEM_BYTES>>>(bih, bhh, out, write_ht);
}

// round 8
// speedup vs baseline: 1.4846x; 1.0962x over previous
#include <cuda_runtime.h>
#include <math.h>

#define NL 4
#define BB 64
#define HH 1024
#define SS 256
#define GHH 512
#define H3 (3*HH)
#define KC 64
#define KCP 68
#define NST 4                   // cp.async pipeline depth (3 tiles in flight)
#define STF (160*KCP)           // floats per stage (max M+TN = 160 rows)
#define NB 148                  // persistent grid: <= SM count, all co-resident
#define NT 512                  // 16 warps
#define SMEM_FLOATS (NST*STF + 2048)
#define SMEM_BYTES (SMEM_FLOATS*4)

// ---------------- device scratch (allocation-free: __device__ globals) ----------------
static __device__ float g_h [NL*BB*HH];
static __device__ float g_hg[NL*BB*HH];
static __device__ float g_sh[NL*BB*HH];
static __device__ float g_gi[NL*BB*H3];
static __device__ float g_gh[NL*BB*H3];
static __device__ float g_gi0[(long)SS*BB*H3];  // precomputed x@Wih0^T + bih0 per t
static __device__ float g_a1[NL*BB*2*HH];
static __device__ float g_a2[NL*BB*2*HH];
static __device__ float g_a3[NL*BB*2*HH];
static __device__ unsigned g_arrive;
static __device__ unsigned g_gen;
// TF32-pre-rounded weights (rounded once, streamed every step)
static __device__ float c_wih[NL*H3*HH];
static __device__ float c_whh[NL*H3*HH];
static __device__ float c_aw0[NL*HH*HH];
static __device__ float c_aw1[NL*GHH*GHH];
static __device__ float c_aw2[NL*GHH*GHH];
static __device__ float c_aw3[NL*HH*2*HH];

// ---------------- software grid barrier -------------------------------------------------
__device__ __forceinline__ void grid_sync()
{
  __syncthreads();
  if (threadIdx.x == 0) {
    unsigned gen = *(volatile unsigned*)&g_gen;
    __threadfence();
    unsigned a = atomicAdd(&g_arrive, 1u);
    if (a == gridDim.x - 1) {
      g_arrive = 0;
      __threadfence();
      *(volatile unsigned*)&g_gen = gen + 1u;
    } else {
      while (*(volatile unsigned*)&g_gen == gen) { __nanosleep(32); }
    }
    __threadfence();
  }
  __syncthreads();
}

// ---------------- helpers ---------------------------------------------------------------
__device__ __forceinline__ unsigned f2tf(float v) {
  unsigned r; asm("cvt.rna.tf32.f32 %0, %1;" : "=r"(r) : "f"(v)); return r;
}
__device__ __forceinline__ void mma8(float* c, unsigned a0, unsigned a1,
                                     unsigned a2, unsigned a3,
                                     unsigned b0, unsigned b1) {
  asm volatile(
    "mma.sync.aligned.m16n8k8.row.col.f32.tf32.tf32.f32 "
    "{%0,%1,%2,%3}, {%4,%5,%6,%7}, {%8,%9}, {%0,%1,%2,%3};"
    : "+f"(c[0]), "+f"(c[1]), "+f"(c[2]), "+f"(c[3])
    : "r"(a0), "r"(a1), "r"(a2), "r"(a3), "r"(b0), "r"(b1));
}
__device__ __forceinline__ void cp16(float* s, const float* g) {
  unsigned a = (unsigned)__cvta_generic_to_shared(s);
  asm volatile("cp.async.cg.shared.global [%0], [%1], 16;" :: "r"(a), "l"(g));
}

// ---------------- M x TN TF32 GEMM, deep cp.async pipeline -----------------------------
// C = A(M,K) @ W(TN,K)^T.  16 warps: wm = wid%MW (16 rows), wn = wid/MW (CW cols).
// W is pre-rounded tf32 bits (raw reads); A is fp32, cvt.rna at fragment read.
// A rows >= 64 come from A1 (fused P3). GATHER folds the SortAttn shuffle into the
// A-load: h = 4u+v -> src = v*512 + g*128 + u, loaded as 4 contiguous 16-float
// segments/row, stored at column v*16 (16B-aligned for cp.async); fragment read
// remaps to col = qc*16 + kk/4 (2-way LDS conflict, acceptable).
template<int MW, int TN, bool GATHER>
__device__ __forceinline__ void gemm_cp(
    const float* __restrict__ A0, const float* __restrict__ A1, long lda,
    const float* __restrict__ W, long ldw, int K, int g,
    float (*acc)[4], float* smf)
{
  constexpr int M = MW*16;
  constexpr int CW = TN*MW/16;
  constexpr int NFR = CW/8;
  const int tid = threadIdx.x;
  const int lane = tid & 31, qr = lane >> 2, qc = lane & 3;
  const int wid = tid >> 5, wm = wid % MW, wn = wid / MW;
  const int mrow = wm*16, nbase = wn*CW;
  const int NK = K / KC;
#pragma unroll
  for (int j = 0; j < NFR; j++) { acc[j][0]=acc[j][1]=acc[j][2]=acc[j][3]=0.f; }

  auto issue = [&](int kt) {
    int k0 = kt * KC;
    float* As = smf + (kt & (NST-1)) * STF;
    float* Ws = As + M*KCP;
    if (!GATHER) {
#pragma unroll
      for (int p = 0; p < M*16/NT; p++) {
        int i = tid + p*NT; int m = i >> 4, c = (i & 15) << 2;
        const float* src = (M > 64 && m >= 64) ? A1 + (long)(m-64)*lda
                                               : A0 + (long)m*lda;
        cp16(As + m*KCP + c, src + k0 + c);
      }
    } else {
      // per row: 4 segments (v) x 4 quarters (q), seg v at column v*16
#pragma unroll
      for (int p = 0; p < 2; p++) {
        int i = tid + p*NT; int m = i >> 4, c = i & 15;
        int v = c >> 2, q = c & 3;
        cp16(As + m*KCP + v*16 + q*4,
             A0 + (long)m*lda + v*512 + g*128 + (k0 >> 2) + q*4);
      }
    }
#pragma unroll
    for (int p = 0; p < TN*16/NT; p++) {
      int i = tid + p*NT; int n = i >> 4, c = (i & 15) << 2;
      cp16(Ws + n*KCP + c, W + (long)n*ldw + k0 + c);
    }
  };

  // prologue: NST-1 stages in flight
#pragma unroll
  for (int kt = 0; kt < NST-1; kt++) {
    if (kt < NK) issue(kt);
    asm volatile("cp.async.commit_group;");
  }
  for (int kt = 0; kt < NK; kt++) {
    asm volatile("cp.async.wait_group %0;" :: "n"(NST-2));
    __syncthreads();
    if (kt + NST-1 < NK) issue(kt + NST-1);
    asm volatile("cp.async.commit_group;");
    const float* As = smf + (kt & (NST-1)) * STF;
    const float* Ws = As + M*KCP;
#pragma unroll
    for (int kk = 0; kk < KC; kk += 8) {
      int ca0 = GATHER ? (qc*16 + (kk >> 2)) : (kk + qc);
      int ca1 = GATHER ? (ca0 + 1)           : (kk + qc + 4);
      unsigned a0 = f2tf(As[(mrow+qr  )*KCP + ca0]);
      unsigned a1 = f2tf(As[(mrow+qr+8)*KCP + ca0]);
      unsigned a2 = f2tf(As[(mrow+qr  )*KCP + ca1]);
      unsigned a3 = f2tf(As[(mrow+qr+8)*KCP + ca1]);
#pragma unroll
      for (int j = 0; j < NFR; j++) {
        unsigned b0 = __float_as_uint(Ws[(nbase+j*8+qr)*KCP + kk+qc  ]);
        unsigned b1 = __float_as_uint(Ws[(nbase+j*8+qr)*KCP + kk+qc+4]);
        mma8(acc[j], a0, a1, a2, a3, b0, b1);
      }
    }
  }
  __syncthreads();   // protect stage smem before next job's prologue
}

// ---------------- init / prep kernels ---------------------------------------------------
__global__ void k_init(const float* __restrict__ h0)
{
  int idx = blockIdx.x*256 + threadIdx.x;
  if (idx == 0) { g_arrive = 0u; g_gen = 0u; }
  int l = idx / (BB*HH);
  int j = idx & (HH-1);
  g_h[idx] = h0[l*HH + j];
}
__global__ void k_round(const float* __restrict__ src, float* __restrict__ dst, int n)
{
  for (int i = blockIdx.x*blockDim.x + threadIdx.x; i < n; i += gridDim.x*blockDim.x)
    dst[i] = __uint_as_float(f2tf(src[i]));
}

// one-time: g_gi0[t] = x[:,t,:] @ Wih0^T + bih0 for all t (layer 0 input GEMM)
__global__ void __launch_bounds__(NT, 1) k_pre(const float* __restrict__ x,
                                               const float* __restrict__ bih)
{
  extern __shared__ float smf[];
  int nt = blockIdx.x, t = blockIdx.y;
  int n0 = nt * 96;
  const float* A = x + (long)t*HH;                  // row b -> x[b*S*H + t*H]
  const float* W = c_wih + (long)n0*HH;             // layer 0
  float* C = g_gi0 + (long)t*BB*H3;
  float acc[3][4];
  gemm_cp<4,96,false>(A, A, (long)SS*HH, W, HH, HH, 0, acc, smf);
  const int tid = threadIdx.x, lane = tid & 31, qr = lane >> 2, qc = lane & 3;
  const int wid = tid >> 5, wm = wid & 3, wn = wid >> 2, mrow = wm*16, nb = wn*24;
#pragma unroll
  for (int j = 0; j < 3; j++) {
    int nl = nb + j*8 + 2*qc;
    float b0v = bih[n0+nl], b1v = bih[n0+nl+1];
    *reinterpret_cast<float2*>(&C[(long)(mrow+qr  )*H3 + n0 + nl]) =
        make_float2(acc[j][0]+b0v, acc[j][1]+b1v);
    *reinterpret_cast<float2*>(&C[(long)(mrow+qr+8)*H3 + n0 + nl]) =
        make_float2(acc[j][2]+b0v, acc[j][3]+b1v);
  }
}

// ---------------- persistent main kernel ------------------------------------------------
__global__ void __launch_bounds__(NT, 1) k_main(
    const float* __restrict__ bih, const float* __restrict__ bhh,
    float* __restrict__ out, int write_ht)
{
  extern __shared__ float smf[];
  float* ssort = smf + NST*STF;
  const int tid = threadIdx.x;
  const int lane = tid & 31, qr = lane >> 2, qc = lane & 3;
  const int wid = tid >> 5;
  const int blk = blockIdx.x;

  for (int step = 0; step < SS + NL - 1; step++) {

    // ---- P1: 7 weight matrices (Wih l=1..3, Whh l=0..3) x 32 N-tiles of 96 = 224 jobs ----
    for (int job = blk; job < 224; job += NB) {
      int mi = job >> 5, nt = job & 31;
      int l, isWih;
      if (mi < 3) { isWih = 1; l = mi + 1; } else { isWih = 0; l = mi - 3; }
      int t = step - l; if (t < 0 || t >= SS) continue;
      int n0 = nt * 96;
      const float* A; const float* W; const float* bias; float* C;
      if (isWih) {
        A = g_h + (long)(l-1)*BB*HH;
        W = c_wih + (long)l*H3*HH + (long)n0*HH;
        bias = bih + l*H3 + n0;  C = g_gi + (long)l*BB*H3;
      } else {
        A = g_h + (long)l*BB*HH;
        W = c_whh + (long)l*H3*HH + (long)n0*HH;
        bias = bhh + l*H3 + n0;  C = g_gh + (long)l*BB*H3;
      }
      float acc[3][4];
      gemm_cp<4,96,false>(A, A, HH, W, HH, HH, 0, acc, smf);
      int wm = wid & 3, wn = wid >> 2, mrow = wm*16, nb = wn*24;
#pragma unroll
      for (int j = 0; j < 3; j++) {
        int nl = nb + j*8 + 2*qc;
        float b0v = bias[nl], b1v = bias[nl+1];
        *reinterpret_cast<float2*>(&C[(long)(mrow+qr  )*H3 + n0 + nl]) =
            make_float2(acc[j][0]+b0v, acc[j][1]+b1v);
        *reinterpret_cast<float2*>(&C[(long)(mrow+qr+8)*H3 + n0 + nl]) =
            make_float2(acc[j][2]+b0v, acc[j][3]+b1v);
      }
    }
    grid_sync();

    // ---- P2: gates + sort. 2 rows/block, 256 threads each, named barriers ----
    if (blk < 128) {
      int h = tid >> 8, htid = tid & 255;
      int jb = blk*2 + h;
      int l = jb >> 6, b = jb & 63;
      int t = step - l;
      if (t >= 0 && t < SS) {
        float* s = ssort + h*1024;
        const float* gi = (l == 0) ? g_gi0 + ((long)t*BB + b)*H3
                                   : g_gi + (long)(l*BB + b)*H3;
        long gb = (long)(l*BB + b)*H3;
        long hb = (long)(l*BB + b)*HH;
#pragma unroll
        for (int p = 0; p < 4; p++) {
          int j = htid + p*256;
          float ir = gi[j], iz = gi[HH + j], in = gi[2*HH + j];
          float hr = g_gh[gb + j], hz = g_gh[gb + HH + j], hn = g_gh[gb + 2*HH + j];
          float rr = 1.f/(1.f + expf(-(ir + hr)));
          float zz = 1.f/(1.f + expf(-(iz + hz)));
          float nn = tanhf(in + rr*hn);
          float hv = (1.f - zz)*nn + zz*g_h[hb + j];
          g_hg[hb + j] = hv;
          s[j] = hv;
        }
        asm volatile("bar.sync %0, 256;" :: "r"(1+h) : "memory");
        for (int size = 2; size <= 1024; size <<= 1) {
          for (int stride = size >> 1; stride; stride >>= 1) {
            if (stride >= 64) asm volatile("bar.sync %0, 256;" :: "r"(1+h) : "memory");
#pragma unroll
            for (int p = 0; p < 2; p++) {
              int q = htid + p*256;
              int pos = 2*q - (q & (stride - 1));
              float a = s[pos], c = s[pos + stride];
              bool desc = (pos & size) != 0;
              if ((a > c) != desc) { s[pos] = c; s[pos + stride] = a; }
            }
            if (stride >= 64) asm volatile("bar.sync %0, 256;" :: "r"(1+h) : "memory");
            else __syncwarp();
          }
        }
#pragma unroll
        for (int p = 0; p < 4; p++) { int j = htid + p*256; g_sh[hb + j] = s[j]; }
      }
    }
    grid_sync();

    // ---- P3: a1 = [hg; sh] @ w0^T  (M=128 fused, TN=32, 128 jobs) ----
    if (blk < 128) {
      int l = blk >> 5, nt = blk & 31;
      int t = step - l;
      if (t >= 0 && t < SS) {
        int n0 = nt * 32;
        const float* W = c_aw0 + (long)l*HH*HH + (long)n0*HH;
        float* C = g_a1 + (long)l*BB*2*HH;
        float acc[2][4];
        gemm_cp<8,32,false>(g_hg + (long)l*BB*HH, g_sh + (long)l*BB*HH, HH,
                            W, HH, HH, 0, acc, smf);
        int wm = wid & 7, wn = wid >> 3, mrow = wm*16, nb = wn*16;
        int y = mrow >> 6, b0r = mrow & 63;
#pragma unroll
        for (int j = 0; j < 2; j++) {
          int nl = nb + j*8 + 2*qc;
          *reinterpret_cast<float2*>(&C[(long)(b0r+qr  )*2*HH + y*HH + n0 + nl]) =
              make_float2(acc[j][0], acc[j][1]);
          *reinterpret_cast<float2*>(&C[(long)(b0r+qr+8)*2*HH + y*HH + n0 + nl]) =
              make_float2(acc[j][2], acc[j][3]);
        }
      }
    }
    grid_sync();

    // ---- P4: w1 GEMM, folded shuffle gather (TN=64, 128 jobs) ----
    if (blk < 128) {
      int l = blk >> 5, g4 = (blk >> 3) & 3, nt = blk & 7;
      int t = step - l;
      if (t >= 0 && t < SS) {
        int n0 = nt * 64;
        const float* A = g_a1 + (long)l*BB*2*HH;
        const float* W = c_aw1 + (long)l*GHH*GHH + (long)n0*GHH;
        float* C = g_a2 + (long)l*BB*2*HH;
        float acc[2][4];
        gemm_cp<4,64,true>(A, A, 2*HH, W, GHH, GHH, g4, acc, smf);
        int wm = wid & 3, wn = wid >> 2, mrow = wm*16, nb = wn*16;
#pragma unroll
        for (int j = 0; j < 2; j++) {
          int nl = nb + j*8 + 2*qc;
          *reinterpret_cast<float2*>(&C[(long)(mrow+qr  )*2*HH + g4*GHH + n0 + nl]) =
              make_float2(acc[j][0], acc[j][1]);
          *reinterpret_cast<float2*>(&C[(long)(mrow+qr+8)*2*HH + g4*GHH + n0 + nl]) =
              make_float2(acc[j][2], acc[j][3]);
        }
      }
    }
    grid_sync();

    // ---- P5: w2 GEMM, folded shuffle gather + ReLU (TN=64, 128 jobs) ----
    if (blk < 128) {
      int l = blk >> 5, g4 = (blk >> 3) & 3, nt = blk & 7;
      int t = step - l;
      if (t >= 0 && t < SS) {
        int n0 = nt * 64;
        const float* A = g_a2 + (long)l*BB*2*HH;
        const float* W = c_aw2 + (long)l*GHH*GHH + (long)n0*GHH;
        float* C = g_a3 + (long)l*BB*2*HH;
        float acc[2][4];
        gemm_cp<4,64,true>(A, A, 2*HH, W, GHH, GHH, g4, acc, smf);
        int wm = wid & 3, wn = wid >> 2, mrow = wm*16, nb = wn*16;
#pragma unroll
        for (int j = 0; j < 2; j++) {
          int nl = nb + j*8 + 2*qc;
          float2 v0 = make_float2(fmaxf(acc[j][0],0.f), fmaxf(acc[j][1],0.f));
          float2 v1 = make_float2(fmaxf(acc[j][2],0.f), fmaxf(acc[j][3],0.f));
          *reinterpret_cast<float2*>(&C[(long)(mrow+qr  )*2*HH + g4*GHH + n0 + nl]) = v0;
          *reinterpret_cast<float2*>(&C[(long)(mrow+qr+8)*2*HH + g4*GHH + n0 + nl]) = v1;
        }
      }
    }
    grid_sync();

    // ---- P6: w3 GEMM (K=2048, TN=32, 128 jobs) + fused sigmoid gate ----
    if (blk < 128) {
      int l = blk >> 5, nt = blk & 31;
      int t = step - l;
      if (t >= 0 && t < SS) {
        int n0 = nt * 32;
        const float* A = g_a3 + (long)l*BB*2*HH;
        const float* W = c_aw3 + (long)l*HH*2*HH + (long)n0*2*HH;
        float acc[1][4];
        gemm_cp<4,32,false>(A, A, 2*HH, W, 2*HH, 2*HH, 0, acc, smf);
        int wm = wid & 3, wn = wid >> 2, mrow = wm*16;
        int nl = wn*8 + 2*qc;
        int n = n0 + nl;
#pragma unroll
        for (int half = 0; half < 2; half++) {
          int b = mrow + qr + half*8;
          long hb = (long)(l*BB + b)*HH + n;
#pragma unroll
          for (int jj = 0; jj < 2; jj++) {
            float a = acc[0][half*2 + jj];
            float res = g_hg[hb + jj] * (1.f/(1.f + expf(-a)));
            g_h[hb + jj] = res;
            if (l == NL-1) out[((long)b*SS + t)*HH + n + jj] = res;
            if (write_ht && t == SS-1) out[(long)BB*SS*HH + hb + jj] = res;
          }
        }
      }
    }
    grid_sync();
  }
}

// ---------------- host ------------------------------------------------------------------
extern "C" void kernel_launch(void* const* d_in, const int* in_sizes, int n_in,
                              void* d_out, int out_size)
{
  const float* x   = (const float*)d_in[0];
  const float* h0  = (const float*)d_in[1];
  const float* Wih = (const float*)d_in[2];
  const float* Whh = (const float*)d_in[3];
  const float* bih = (const float*)d_in[4];
  const float* bhh = (const float*)d_in[5];
  const float* aw0 = (const float*)d_in[6];
  const float* aw1 = (const float*)d_in[7];
  const float* aw2 = (const float*)d_in[8];
  const float* aw3 = (const float*)d_in[9];
  float* out = (float*)d_out;

  int write_ht = (out_size >= BB*SS*HH + NL*BB*HH) ? 1 : 0;

  cudaFuncSetAttribute(k_pre,  cudaFuncAttributeMaxDynamicSharedMemorySize, SMEM_BYTES);
  cudaFuncSetAttribute(k_main, cudaFuncAttributeMaxDynamicSharedMemorySize, SMEM_BYTES);

  // round weights to tf32 once
  float* dsts[6]; const float* srcs[6]; int ns[6];
  cudaGetSymbolAddress((void**)&dsts[0], c_wih); srcs[0] = Wih; ns[0] = NL*H3*HH;
  cudaGetSymbolAddress((void**)&dsts[1], c_whh); srcs[1] = Whh; ns[1] = NL*H3*HH;
  cudaGetSymbolAddress((void**)&dsts[2], c_aw0); srcs[2] = aw0; ns[2] = NL*HH*HH;
  cudaGetSymbolAddress((void**)&dsts[3], c_aw1); srcs[3] = aw1; ns[3] = NL*GHH*GHH;
  cudaGetSymbolAddress((void**)&dsts[4], c_aw2); srcs[4] = aw2; ns[4] = NL*GHH*GHH;
  cudaGetSymbolAddress((void**)&dsts[5], c_aw3); srcs[5] = aw3; ns[5] = NL*HH*2*HH;
  for (int i = 0; i < 6; i++)
    k_round<<<512, 256>>>(srcs[i], dsts[i], ns[i]);

  k_init<<<NL*BB*HH/256, 256>>>(h0);
  k_pre<<<dim3(32, 256), NT, SMEM_BYTES>>>(x, bih);     // layer-0 input GEMM, all t
  k_main<<<NB, NT, SMEM_BYTES>>>(bih, bhh, out, write_ht);
}